// round 13
// baseline (speedup 1.0000x reference)
#include <cuda_runtime.h>
#include <cuda_fp16.h>
#include <cstdint>

#define B_  2
#define S_  4096
#define H_  8
#define DH_ 64
#define D_  512
#define M_  (B_*S_)   // 8192

// Scratch (allocation-free rule: __device__ globals)
__device__ __half g_Xh[M_*D_];    // X converted to half [token][dim]
__device__ __half g_Wt[4*D_*D_];  // Wq,Wk,Wv,Wo transposed to [n][k], half
__device__ __half g_Q[M_*D_];     // [token][dim], pre-scaled by 1/8
__device__ __half g_K[M_*D_];     // [token][dim]
__device__ __half g_V[M_*D_];     // TRANSPOSED [dim][token], tokens pair-permuted per 16-group
__device__ __half g_Ctxh[M_*D_];  // attention output, half [token][dim]

__device__ __forceinline__ float ex2f(float x) {
    float r;
    asm("ex2.approx.ftz.f32 %0, %1;" : "=f"(r) : "f"(x));
    return r;
}

// pack two fp32 -> f16x2 word (lo = first arg, hi = second arg)
__device__ __forceinline__ uint32_t pack_h2(float lo, float hi) {
    uint32_t r;
    asm("cvt.rn.f16x2.f32 %0, %1, %2;" : "=r"(r) : "f"(hi), "f"(lo));
    return r;
}

// fp16 mma m16n8k16: a = 4x f16x2, b = 2x f16x2, fp32 accum
__device__ __forceinline__ void mma_f16(float c[4],
                                        uint32_t a0, uint32_t a1, uint32_t a2, uint32_t a3,
                                        uint32_t b0, uint32_t b1) {
    asm volatile(
        "mma.sync.aligned.m16n8k16.row.col.f32.f16.f16.f32 "
        "{%0,%1,%2,%3}, {%4,%5,%6,%7}, {%8,%9}, {%0,%1,%2,%3};\n"
        : "+f"(c[0]), "+f"(c[1]), "+f"(c[2]), "+f"(c[3])
        : "r"(a0), "r"(a1), "r"(a2), "r"(a3), "r"(b0), "r"(b1));
}

__device__ __forceinline__ void cp16(void* dst_smem, const void* src_gmem) {
    uint32_t d = (uint32_t)__cvta_generic_to_shared(dst_smem);
    asm volatile("cp.async.cg.shared.global [%0], [%1], 16;" :: "r"(d), "l"(src_gmem));
}
#define CP_COMMIT() asm volatile("cp.async.commit_group;")
#define CP_WAIT1()  asm volatile("cp.async.wait_group 1;")
#define CP_WAIT0()  asm volatile("cp.async.wait_group 0;")

// token permutation within 16-group: pair p -> slot (p<4 ? 2p : 2(p-4)+1)
__device__ __forceinline__ int vperm(int tok) {
    int p  = (tok >> 1) & 7;
    int pp = (p < 4) ? (2*p) : (2*(p-4)+1);
    return (tok & ~15) | (pp << 1) | (tok & 1);
}

// ---------------------------------------------------------------------------
// Prep (fused): blocks [0, 8192) convert X fp32->half; blocks [8192, 9216)
// transpose+convert the 4 weight matrices to Wt [n][k] half.
// ---------------------------------------------------------------------------
#define XBLOCKS (M_*D_/2/256)   // 8192

__global__ __launch_bounds__(256) void prep(const float* __restrict__ X,
                                            const float* __restrict__ W0,
                                            const float* __restrict__ W1,
                                            const float* __restrict__ W2,
                                            const float* __restrict__ W3)
{
    __shared__ float tl[32][33];
    if (blockIdx.x < XBLOCKS) {
        int i = blockIdx.x * 256 + threadIdx.x;
        float2 v = ((const float2*)X)[i];
        ((uint32_t*)g_Xh)[i] = pack_h2(v.x, v.y);
    } else {
        int bid = blockIdx.x - XBLOCKS;        // 0..1023
        int z = bid >> 8;
        int bx = bid & 15, by = (bid >> 4) & 15;
        const float* W = (z == 0) ? W0 : (z == 1) ? W1 : (z == 2) ? W2 : W3;
        __half* Wt = g_Wt + (size_t)z * D_ * D_;
        int n0 = bx * 32, k0 = by * 32;
        int tx = threadIdx.x & 31, ty = threadIdx.x >> 5;   // 32 x 8
        #pragma unroll
        for (int j = 0; j < 32; j += 8)
            tl[ty + j][tx] = W[(size_t)(k0 + ty + j) * D_ + n0 + tx];
        __syncthreads();
        #pragma unroll
        for (int j = 0; j < 32; j += 8)
            Wt[(size_t)(n0 + ty + j) * D_ + k0 + tx] = __float2half_rn(tl[tx][ty + j]);
    }
}

// ---------------------------------------------------------------------------
// fp16 GEMM: C[M,512] = A[M,512] @ Wt^T + bias, m16n8k16, pairwise k-relabel.
// 128x128 tile/CTA, 256 threads, 8 warps (4x2), warp tile 32x64.
// k-tile 64 halves (8 iters of ~2048-cyc compute -> prefetch window covers
// DRAM latency), 2-stage, ONE sync per iter, 2 CTAs/SM.
// Smem: 2 stages x (A[128][40] + B[128][40]) words = 80 KB dynamic.
// mode 0: g_Q (acc+b)/8;  1: g_K;  2: g_V transposed+permuted;  3: Cout fp32.
// ---------------------------------------------------------------------------
#define GST 40                    // words per smem row (32 data + 8 pad)
#define ASTG (128*GST)            // words per matrix per stage

__global__ __launch_bounds__(256, 2) void gemm_h(const float* __restrict__ b0,
                                                 const float* __restrict__ b1,
                                                 const float* __restrict__ b2,
                                                 float* __restrict__ Cout,
                                                 int modesel)
{
    extern __shared__ uint32_t smg[];   // [2][2*ASTG] : stage -> {A, B}

    int mode = (modesel >= 0) ? modesel : (int)blockIdx.z;
    const float* bias = (mode == 0 || mode == 3) ? b0 : (mode == 1 ? b1 : b2);
    const __half* A  = (mode == 3) ? g_Ctxh : g_Xh;
    const __half* Bw = g_Wt + (size_t)mode * D_ * D_;

    int t = threadIdx.x, w = t >> 5, lane = t & 31;
    int g = lane >> 2, c = lane & 3;
    int wm = w & 3, wn = w >> 2;
    int m0 = blockIdx.x * 128, n0 = blockIdx.y * 128;

    auto issue = [&](int kt, int buf) {
        int k0 = kt * 64;
        uint32_t* Ad = smg + buf * 2 * ASTG;
        uint32_t* Bd = Ad + ASTG;
        #pragma unroll
        for (int it = 0; it < 4; ++it) {
            int idx = t + it * 256;                // 0..1023
            int r = idx >> 3, cc = idx & 7;        // 128 rows x 8 chunks
            cp16(Ad + r*GST + cc*4, A  + (size_t)(m0 + r) * D_ + k0 + cc*8);
            cp16(Bd + r*GST + cc*4, Bw + (size_t)(n0 + r) * D_ + k0 + cc*8);
        }
    };
    issue(0, 0); CP_COMMIT();

    float acc[2][8][4];
    #pragma unroll
    for (int mb = 0; mb < 2; ++mb)
        #pragma unroll
        for (int nb = 0; nb < 8; ++nb)
            #pragma unroll
            for (int j = 0; j < 4; ++j) acc[mb][nb][j] = 0.0f;

    for (int kt = 0; kt < 8; ++kt) {
        CP_WAIT0(); __syncthreads();          // stage kt ready; compute kt-1 retired
        if (kt + 1 < 8) { issue(kt + 1, (kt + 1) & 1); CP_COMMIT(); }
        const uint32_t* Ab = smg + (kt & 1) * 2 * ASTG;
        const uint32_t* Bb = Ab + ASTG;
        #pragma unroll
        for (int s = 0; s < 4; ++s) {
            uint2 a0 = *(const uint2*)(Ab + (32*wm + g)      * GST + s*8 + 2*c);
            uint2 a1 = *(const uint2*)(Ab + (32*wm + 8 + g)  * GST + s*8 + 2*c);
            uint2 a2 = *(const uint2*)(Ab + (32*wm + 16 + g) * GST + s*8 + 2*c);
            uint2 a3 = *(const uint2*)(Ab + (32*wm + 24 + g) * GST + s*8 + 2*c);
            #pragma unroll
            for (int nb = 0; nb < 8; ++nb) {
                uint2 bb = *(const uint2*)(Bb + (64*wn + 8*nb + g) * GST + s*8 + 2*c);
                mma_f16(acc[0][nb], a0.x, a1.x, a0.y, a1.y, bb.x, bb.y);
                mma_f16(acc[1][nb], a2.x, a3.x, a2.y, a3.y, bb.x, bb.y);
            }
        }
    }

    // Epilogue
    #pragma unroll
    for (int mb = 0; mb < 2; ++mb) {
        int row = m0 + 32*wm + 16*mb + g;
        #pragma unroll
        for (int nb = 0; nb < 8; ++nb) {
            int col = n0 + 64*wn + 8*nb + 2*c;
            float bv0 = bias[col], bv1 = bias[col + 1];
            float v0 = acc[mb][nb][0] + bv0;
            float v1 = acc[mb][nb][1] + bv1;
            float v2 = acc[mb][nb][2] + bv0;
            float v3 = acc[mb][nb][3] + bv1;
            if (mode == 0) {
                *(uint32_t*)(g_Q + (size_t)row * D_ + col) =
                    pack_h2(v0 * 0.125f, v1 * 0.125f);
                *(uint32_t*)(g_Q + (size_t)(row + 8) * D_ + col) =
                    pack_h2(v2 * 0.125f, v3 * 0.125f);
            } else if (mode == 1) {
                *(uint32_t*)(g_K + (size_t)row * D_ + col)       = pack_h2(v0, v1);
                *(uint32_t*)(g_K + (size_t)(row + 8) * D_ + col) = pack_h2(v2, v3);
            } else if (mode == 2) {
                g_V[(size_t)col       * M_ + vperm(row)]     = __float2half_rn(v0);
                g_V[(size_t)(col + 1) * M_ + vperm(row)]     = __float2half_rn(v1);
                g_V[(size_t)col       * M_ + vperm(row + 8)] = __float2half_rn(v2);
                g_V[(size_t)(col + 1) * M_ + vperm(row + 8)] = __float2half_rn(v3);
            } else {
                *(float2*)(Cout + (size_t)row * D_ + col)       = make_float2(v0, v1);
                *(float2*)(Cout + (size_t)(row + 8) * D_ + col) = make_float2(v2, v3);
            }
        }
    }
}

// ---------------------------------------------------------------------------
// Flash attention, fp16 mma m16n8k16, pairwise k-relabel, no-max softmax,
// deferred l-reduction, Q fragments register-hoisted.
// 256 threads (8 warps), 256 queries/CTA, warp w = rows 32w..32w+31.
// 64-key tiles, triple-buffered cp.async, one sync per tile.
// Warps w>=4 iterate the exp/PV st-loop in REVERSE so the two warps sharing
// an SMSP (w, w+4) stagger their MUFU bursts against each other's HMMA.
// ---------------------------------------------------------------------------
#define QW 40
#define LOG2E 1.4426950408889634f

__global__ __launch_bounds__(256, 1) void attn_h()
{
    extern __shared__ char smc[];
    uint32_t* Qw = (uint32_t*)smc;                 // [256][QW]
    uint32_t* Kw = Qw + 256*QW;                    // [3][64][QW]
    uint32_t* Vw = Kw + 3*64*QW;                   // [3][64][QW]

    int t = threadIdx.x, w = t >> 5, lane = t & 31;
    int g = lane >> 2, c = lane & 3;
    int b = blockIdx.z, h = blockIdx.y;
    int q0 = blockIdx.x * 256;
    int rev = (w >> 2) & 1;                        // SMSP-partner staggering

    const __half* Qg  = g_Q + (size_t)(b * S_ + q0) * D_ + h * DH_;
    const __half* Kg  = g_K + (size_t)b * S_ * D_ + h * DH_;
    const __half* Vtg = g_V + (size_t)(h * DH_) * M_ + b * S_;   // [dim][token]

    auto issue_kv = [&](int kt, int buf) {
        uint32_t* kd = Kw + buf * 64 * QW;
        uint32_t* vd = Vw + buf * 64 * QW;
        #pragma unroll
        for (int it = 0; it < 2; ++it) {
            int idx = t + it * 256;
            int row = idx >> 3, c4 = idx & 7;
            cp16(kd + row*QW + c4*4, Kg + (size_t)(kt*64 + row) * D_ + c4*8);
            cp16(vd + row*QW + c4*4, Vtg + (size_t)row * M_ + kt*64 + c4*8);
        }
    };

    // Prologue: G0 = Q + KV0; G1 = KV1
    #pragma unroll
    for (int it = 0; it < 8; ++it) {
        int idx = t + it * 256;
        int row = idx >> 3, c4 = idx & 7;
        cp16(Qw + row*QW + c4*4, Qg + (size_t)row * D_ + c4*8);
    }
    issue_kv(0, 0); CP_COMMIT();
    issue_kv(1, 1); CP_COMMIT();

    CP_WAIT1(); __syncthreads();     // G0 (Q + KV0) complete

    // Hoist Q fragments: qf[kk][mb][i], i=0 -> row 32w+16mb+g, i=1 -> +8
    uint2 qf[4][2][2];
    #pragma unroll
    for (int kk = 0; kk < 4; ++kk)
        #pragma unroll
        for (int mb = 0; mb < 2; ++mb) {
            qf[kk][mb][0] = *(const uint2*)(Qw + (32*w + 16*mb + g)     * QW + kk*8 + 2*c);
            qf[kk][mb][1] = *(const uint2*)(Qw + (32*w + 16*mb + 8 + g) * QW + kk*8 + 2*c);
        }

    float o[2][8][4];
    #pragma unroll
    for (int mb = 0; mb < 2; ++mb)
        #pragma unroll
        for (int nb = 0; nb < 8; ++nb)
            #pragma unroll
            for (int j = 0; j < 4; ++j) o[mb][nb][j] = 0.0f;
    float lsum[2][2] = {{0.0f, 0.0f}, {0.0f, 0.0f}};

    for (int kt = 0; kt < S_ / 64; ++kt) {
        if (kt > 0) { CP_WAIT1(); __syncthreads(); }   // buf kt ready; iter kt-1 retired
        if (kt + 2 < S_ / 64) issue_kv(kt + 2, (kt + 2) % 3);
        CP_COMMIT();
        const uint32_t* bufK = Kw + (kt % 3) * 64 * QW;
        const uint32_t* bufV = Vw + (kt % 3) * 64 * QW;

        // ---- S = Q @ K^T (32 rows x 64 keys per warp) ----
        float s[2][8][4];
        #pragma unroll
        for (int mb = 0; mb < 2; ++mb)
            #pragma unroll
            for (int nb = 0; nb < 8; ++nb)
                #pragma unroll
                for (int j = 0; j < 4; ++j) s[mb][nb][j] = 0.0f;

        #pragma unroll
        for (int kk = 0; kk < 4; ++kk) {
            #pragma unroll
            for (int nb = 0; nb < 8; ++nb) {
                uint2 bb = *(const uint2*)(bufK + (8*nb + g) * QW + kk*8 + 2*c);
                mma_f16(s[0][nb], qf[kk][0][0].x, qf[kk][0][1].x,
                                  qf[kk][0][0].y, qf[kk][0][1].y, bb.x, bb.y);
                mma_f16(s[1][nb], qf[kk][1][0].x, qf[kk][1][1].x,
                                  qf[kk][1][0].y, qf[kk][1][1].y, bb.x, bb.y);
            }
        }

        // ---- fused exp + PV (st order staggered across SMSP partners) ----
        #pragma unroll
        for (int sti = 0; sti < 4; ++sti) {
            int st = rev ? (3 - sti) : sti;
            uint32_t a[2][4];
            #pragma unroll
            for (int mb = 0; mb < 2; ++mb) {
                float e00 = ex2f(s[mb][2*st][0]   * LOG2E);
                float e01 = ex2f(s[mb][2*st][1]   * LOG2E);
                float e02 = ex2f(s[mb][2*st][2]   * LOG2E);
                float e03 = ex2f(s[mb][2*st][3]   * LOG2E);
                float e10 = ex2f(s[mb][2*st+1][0] * LOG2E);
                float e11 = ex2f(s[mb][2*st+1][1] * LOG2E);
                float e12 = ex2f(s[mb][2*st+1][2] * LOG2E);
                float e13 = ex2f(s[mb][2*st+1][3] * LOG2E);
                lsum[mb][0] += e00 + e01 + e10 + e11;
                lsum[mb][1] += e02 + e03 + e12 + e13;
                a[mb][0] = pack_h2(e00, e01);
                a[mb][1] = pack_h2(e02, e03);
                a[mb][2] = pack_h2(e10, e11);
                a[mb][3] = pack_h2(e12, e13);
            }
            #pragma unroll
            for (int nbd = 0; nbd < 8; ++nbd) {
                uint2 vv = *(const uint2*)(bufV + (8*nbd + g) * QW + st*8 + 2*c);
                mma_f16(o[0][nbd], a[0][0], a[0][1], a[0][2], a[0][3], vv.x, vv.y);
                mma_f16(o[1][nbd], a[1][0], a[1][1], a[1][2], a[1][3], vv.x, vv.y);
            }
        }
    }

    // ---- epilogue: reduce l over quad, normalize, write half context ----
    float inv[2][2];
    #pragma unroll
    for (int mb = 0; mb < 2; ++mb)
        #pragma unroll
        for (int hh = 0; hh < 2; ++hh) {
            float v = lsum[mb][hh];
            v += __shfl_xor_sync(0xffffffffu, v, 1);
            v += __shfl_xor_sync(0xffffffffu, v, 2);
            inv[mb][hh] = 1.0f / v;
        }

    __half* Og = g_Ctxh + (size_t)(b * S_ + q0) * D_ + h * DH_;
    #pragma unroll
    for (int mb = 0; mb < 2; ++mb) {
        int r0 = 32*w + 16*mb + g;
        #pragma unroll
        for (int nbd = 0; nbd < 8; ++nbd) {
            int col = 8*nbd + 2*c;
            *(uint32_t*)(Og + (size_t)r0 * D_ + col) =
                pack_h2(o[mb][nbd][0] * inv[mb][0], o[mb][nbd][1] * inv[mb][0]);
            *(uint32_t*)(Og + (size_t)(r0 + 8) * D_ + col) =
                pack_h2(o[mb][nbd][2] * inv[mb][1], o[mb][nbd][3] * inv[mb][1]);
        }
    }
}

// ---------------------------------------------------------------------------
extern "C" void kernel_launch(void* const* d_in, const int* in_sizes, int n_in,
                              void* d_out, int out_size)
{
    const float* X  = (const float*)d_in[0];
    const float* Wq = (const float*)d_in[1];
    const float* bq = (const float*)d_in[2];
    const float* Wk = (const float*)d_in[3];
    const float* bk = (const float*)d_in[4];
    const float* Wv = (const float*)d_in[5];
    const float* bv = (const float*)d_in[6];
    const float* Wo = (const float*)d_in[7];
    const float* bo = (const float*)d_in[8];
    float* out = (float*)d_out;

    prep<<<XBLOCKS + 1024, 256>>>(X, Wq, Wk, Wv, Wo);

    size_t gsm = (size_t)4 * ASTG * sizeof(uint32_t);  // 81,920 B
    cudaFuncSetAttribute(gemm_h, cudaFuncAttributeMaxDynamicSharedMemorySize, (int)gsm);
    gemm_h<<<dim3(M_/128, D_/128, 3), 256, gsm>>>(bq, bk, bv, nullptr, -1);

    size_t shm = (size_t)(256*QW + 3*64*QW + 3*64*QW) * sizeof(uint32_t);  // 102,400 B
    cudaFuncSetAttribute(attn_h, cudaFuncAttributeMaxDynamicSharedMemorySize, (int)shm);
    attn_h<<<dim3(S_ / 256, H_, B_), 256, shm>>>();

    gemm_h<<<dim3(M_/128, D_/128), 256, gsm>>>(bo, nullptr, nullptr, out, 3);
}

// round 14
// speedup vs baseline: 1.3882x; 1.3882x over previous
#include <cuda_runtime.h>
#include <cuda_fp16.h>
#include <cstdint>

#define B_  2
#define S_  4096
#define H_  8
#define DH_ 64
#define D_  512
#define M_  (B_*S_)   // 8192

// Scratch (allocation-free rule: __device__ globals)
__device__ __half g_Xh[M_*D_];    // X converted to half [token][dim]
__device__ __half g_Wt[4*D_*D_];  // Wq,Wk,Wv,Wo transposed to [n][k], half
__device__ __half g_Q[M_*D_];     // [token][dim], pre-scaled by 1/8
__device__ __half g_K[M_*D_];     // [token][dim]
__device__ __half g_V[M_*D_];     // TRANSPOSED [dim][token], tokens pair-permuted per 16-group
__device__ __half g_Ctxh[M_*D_];  // attention output, half [token][dim]

__device__ __forceinline__ float ex2f(float x) {
    float r;
    asm("ex2.approx.ftz.f32 %0, %1;" : "=f"(r) : "f"(x));
    return r;
}

// pack two fp32 -> f16x2 word (lo = first arg, hi = second arg)
__device__ __forceinline__ uint32_t pack_h2(float lo, float hi) {
    uint32_t r;
    asm("cvt.rn.f16x2.f32 %0, %1, %2;" : "=r"(r) : "f"(hi), "f"(lo));
    return r;
}

// fp16 mma m16n8k16: a = 4x f16x2, b = 2x f16x2, fp32 accum
__device__ __forceinline__ void mma_f16(float c[4],
                                        uint32_t a0, uint32_t a1, uint32_t a2, uint32_t a3,
                                        uint32_t b0, uint32_t b1) {
    asm volatile(
        "mma.sync.aligned.m16n8k16.row.col.f32.f16.f16.f32 "
        "{%0,%1,%2,%3}, {%4,%5,%6,%7}, {%8,%9}, {%0,%1,%2,%3};\n"
        : "+f"(c[0]), "+f"(c[1]), "+f"(c[2]), "+f"(c[3])
        : "r"(a0), "r"(a1), "r"(a2), "r"(a3), "r"(b0), "r"(b1));
}

__device__ __forceinline__ void cp16(void* dst_smem, const void* src_gmem) {
    uint32_t d = (uint32_t)__cvta_generic_to_shared(dst_smem);
    asm volatile("cp.async.cg.shared.global [%0], [%1], 16;" :: "r"(d), "l"(src_gmem));
}
#define CP_COMMIT() asm volatile("cp.async.commit_group;")
#define CP_WAIT1()  asm volatile("cp.async.wait_group 1;")

// token permutation within 16-group: pair p -> slot (p<4 ? 2p : 2(p-4)+1)
__device__ __forceinline__ int vperm(int tok) {
    int p  = (tok >> 1) & 7;
    int pp = (p < 4) ? (2*p) : (2*(p-4)+1);
    return (tok & ~15) | (pp << 1) | (tok & 1);
}

// ---------------------------------------------------------------------------
// Prep (fused): blocks [0, 8192) convert X fp32->half; blocks [8192, 9216)
// transpose+convert the 4 weight matrices to Wt [n][k] half.
// ---------------------------------------------------------------------------
#define XBLOCKS (M_*D_/2/256)   // 8192

__global__ __launch_bounds__(256) void prep(const float* __restrict__ X,
                                            const float* __restrict__ W0,
                                            const float* __restrict__ W1,
                                            const float* __restrict__ W2,
                                            const float* __restrict__ W3)
{
    __shared__ float tl[32][33];
    if (blockIdx.x < XBLOCKS) {
        int i = blockIdx.x * 256 + threadIdx.x;
        float2 v = ((const float2*)X)[i];
        ((uint32_t*)g_Xh)[i] = pack_h2(v.x, v.y);
    } else {
        int bid = blockIdx.x - XBLOCKS;        // 0..1023
        int z = bid >> 8;
        int bx = bid & 15, by = (bid >> 4) & 15;
        const float* W = (z == 0) ? W0 : (z == 1) ? W1 : (z == 2) ? W2 : W3;
        __half* Wt = g_Wt + (size_t)z * D_ * D_;
        int n0 = bx * 32, k0 = by * 32;
        int tx = threadIdx.x & 31, ty = threadIdx.x >> 5;   // 32 x 8
        #pragma unroll
        for (int j = 0; j < 32; j += 8)
            tl[ty + j][tx] = W[(size_t)(k0 + ty + j) * D_ + n0 + tx];
        __syncthreads();
        #pragma unroll
        for (int j = 0; j < 32; j += 8)
            Wt[(size_t)(n0 + ty + j) * D_ + k0 + tx] = __float2half_rn(tl[tx][ty + j]);
    }
}

// ---------------------------------------------------------------------------
// fp16 GEMM (R12 known-good): C = A @ Wt^T + bias, m16n8k16, pair k-relabel.
// 128x128 tile/CTA, 256 threads, 8 warps (4x2), warp tile 32x64.
// k-tile 32, TRIPLE-buffered cp.async, ONE sync per k-iter.
// modesel = -1: mode from blockIdx.z (fused QKV); modesel = 3: O-proj.
// ---------------------------------------------------------------------------
#define HST 24
#define GSTAGE (128*HST)

__global__ __launch_bounds__(256, 1) void gemm_h(const float* __restrict__ b0,
                                                 const float* __restrict__ b1,
                                                 const float* __restrict__ b2,
                                                 float* __restrict__ Cout,
                                                 int modesel)
{
    extern __shared__ uint32_t smg[];
    uint32_t* Ah = smg;                 // [3][128*HST]
    uint32_t* Bh = smg + 3*GSTAGE;      // [3][128*HST]

    int mode = (modesel >= 0) ? modesel : (int)blockIdx.z;
    const float* bias = (mode == 0 || mode == 3) ? b0 : (mode == 1 ? b1 : b2);
    const __half* A  = (mode == 3) ? g_Ctxh : g_Xh;
    const __half* Bw = g_Wt + (size_t)mode * D_ * D_;

    int t = threadIdx.x, w = t >> 5, lane = t & 31;
    int g = lane >> 2, c = lane & 3;
    int wm = w & 3, wn = w >> 2;
    int m0 = blockIdx.x * 128, n0 = blockIdx.y * 128;

    auto issue = [&](int kt, int buf) {
        int k0 = kt * 32;
        #pragma unroll
        for (int it = 0; it < 2; ++it) {
            int idx = t + it * 256;
            int r = idx >> 2, cc = idx & 3;
            cp16(Ah + buf*GSTAGE + r*HST + cc*4, A  + (size_t)(m0 + r) * D_ + k0 + cc*8);
            cp16(Bh + buf*GSTAGE + r*HST + cc*4, Bw + (size_t)(n0 + r) * D_ + k0 + cc*8);
        }
    };
    issue(0, 0); CP_COMMIT();
    issue(1, 1); CP_COMMIT();

    float acc[2][8][4];
    #pragma unroll
    for (int mb = 0; mb < 2; ++mb)
        #pragma unroll
        for (int nb = 0; nb < 8; ++nb)
            #pragma unroll
            for (int j = 0; j < 4; ++j) acc[mb][nb][j] = 0.0f;

    for (int kt = 0; kt < 16; ++kt) {
        CP_WAIT1(); __syncthreads();                  // buf kt ready; iter kt-1 retired
        if (kt + 2 < 16) issue(kt + 2, (kt + 2) % 3); // target buf read in iter kt-1
        CP_COMMIT();
        const uint32_t* Ab = Ah + (kt % 3) * GSTAGE;
        const uint32_t* Bb = Bh + (kt % 3) * GSTAGE;
        #pragma unroll
        for (int s = 0; s < 2; ++s) {
            uint2 a0 = *(const uint2*)(Ab + (32*wm + g)      * HST + s*8 + 2*c);
            uint2 a1 = *(const uint2*)(Ab + (32*wm + 8 + g)  * HST + s*8 + 2*c);
            uint2 a2 = *(const uint2*)(Ab + (32*wm + 16 + g) * HST + s*8 + 2*c);
            uint2 a3 = *(const uint2*)(Ab + (32*wm + 24 + g) * HST + s*8 + 2*c);
            #pragma unroll
            for (int nb = 0; nb < 8; ++nb) {
                uint2 bb = *(const uint2*)(Bb + (64*wn + 8*nb + g) * HST + s*8 + 2*c);
                mma_f16(acc[0][nb], a0.x, a1.x, a0.y, a1.y, bb.x, bb.y);
                mma_f16(acc[1][nb], a2.x, a3.x, a2.y, a3.y, bb.x, bb.y);
            }
        }
    }

    // Epilogue
    #pragma unroll
    for (int mb = 0; mb < 2; ++mb) {
        int row = m0 + 32*wm + 16*mb + g;
        #pragma unroll
        for (int nb = 0; nb < 8; ++nb) {
            int col = n0 + 64*wn + 8*nb + 2*c;
            float bv0 = bias[col], bv1 = bias[col + 1];
            float v0 = acc[mb][nb][0] + bv0;
            float v1 = acc[mb][nb][1] + bv1;
            float v2 = acc[mb][nb][2] + bv0;
            float v3 = acc[mb][nb][3] + bv1;
            if (mode == 0) {
                *(uint32_t*)(g_Q + (size_t)row * D_ + col) =
                    pack_h2(v0 * 0.125f, v1 * 0.125f);
                *(uint32_t*)(g_Q + (size_t)(row + 8) * D_ + col) =
                    pack_h2(v2 * 0.125f, v3 * 0.125f);
            } else if (mode == 1) {
                *(uint32_t*)(g_K + (size_t)row * D_ + col)       = pack_h2(v0, v1);
                *(uint32_t*)(g_K + (size_t)(row + 8) * D_ + col) = pack_h2(v2, v3);
            } else if (mode == 2) {
                g_V[(size_t)col       * M_ + vperm(row)]     = __float2half_rn(v0);
                g_V[(size_t)(col + 1) * M_ + vperm(row)]     = __float2half_rn(v1);
                g_V[(size_t)col       * M_ + vperm(row + 8)] = __float2half_rn(v2);
                g_V[(size_t)(col + 1) * M_ + vperm(row + 8)] = __float2half_rn(v3);
            } else {
                *(float2*)(Cout + (size_t)row * D_ + col)       = make_float2(v0, v1);
                *(float2*)(Cout + (size_t)(row + 8) * D_ + col) = make_float2(v2, v3);
            }
        }
    }
}

// ---------------------------------------------------------------------------
// Flash attention (R12 per-warp code, 2-CTA/SM grouping).
// 128 threads (4 warps), 128 queries/CTA, warp w = rows 32w..32w+31.
// Smem 80 KB -> 2 CTAs co-resident/SM: one CTA's sync/MUFU/wait gaps are
// filled by the other's HMMA. Per-warp math identical to R12.
// 64-key tiles, triple-buffered cp.async, one sync per tile.
// ---------------------------------------------------------------------------
#define QW 40
#define ATH 128
#define LOG2E 1.4426950408889634f

__global__ __launch_bounds__(ATH, 2) void attn_h()
{
    extern __shared__ char smc[];
    uint32_t* Qw = (uint32_t*)smc;                 // [128][QW]  5120 words
    uint32_t* Kw = Qw + 128*QW;                    // [3][64][QW] 7680 words
    uint32_t* Vw = Kw + 3*64*QW;                   // [3][64][QW] 7680 words

    int t = threadIdx.x, w = t >> 5, lane = t & 31;
    int g = lane >> 2, c = lane & 3;
    int b = blockIdx.z, h = blockIdx.y;
    int q0 = blockIdx.x * 128;

    const __half* Qg  = g_Q + (size_t)(b * S_ + q0) * D_ + h * DH_;
    const __half* Kg  = g_K + (size_t)b * S_ * D_ + h * DH_;
    const __half* Vtg = g_V + (size_t)(h * DH_) * M_ + b * S_;   // [dim][token]

    auto issue_kv = [&](int kt, int buf) {
        uint32_t* kd = Kw + buf * 64 * QW;
        uint32_t* vd = Vw + buf * 64 * QW;
        #pragma unroll
        for (int it = 0; it < 4; ++it) {
            int idx = t + it * ATH;
            int row = idx >> 3, c4 = idx & 7;
            cp16(kd + row*QW + c4*4, Kg + (size_t)(kt*64 + row) * D_ + c4*8);
            cp16(vd + row*QW + c4*4, Vtg + (size_t)row * M_ + kt*64 + c4*8);
        }
    };

    // Prologue: G0 = Q + KV0; G1 = KV1
    #pragma unroll
    for (int it = 0; it < 8; ++it) {
        int idx = t + it * ATH;
        int row = idx >> 3, c4 = idx & 7;
        cp16(Qw + row*QW + c4*4, Qg + (size_t)row * D_ + c4*8);
    }
    issue_kv(0, 0); CP_COMMIT();
    issue_kv(1, 1); CP_COMMIT();

    CP_WAIT1(); __syncthreads();     // G0 (Q + KV0) complete

    // Hoist Q fragments: qf[kk][mb][i], i=0 -> row 32w+16mb+g, i=1 -> +8
    uint2 qf[4][2][2];
    #pragma unroll
    for (int kk = 0; kk < 4; ++kk)
        #pragma unroll
        for (int mb = 0; mb < 2; ++mb) {
            qf[kk][mb][0] = *(const uint2*)(Qw + (32*w + 16*mb + g)     * QW + kk*8 + 2*c);
            qf[kk][mb][1] = *(const uint2*)(Qw + (32*w + 16*mb + 8 + g) * QW + kk*8 + 2*c);
        }

    float o[2][8][4];
    #pragma unroll
    for (int mb = 0; mb < 2; ++mb)
        #pragma unroll
        for (int nb = 0; nb < 8; ++nb)
            #pragma unroll
            for (int j = 0; j < 4; ++j) o[mb][nb][j] = 0.0f;
    float lsum[2][2] = {{0.0f, 0.0f}, {0.0f, 0.0f}};

    for (int kt = 0; kt < S_ / 64; ++kt) {
        if (kt > 0) { CP_WAIT1(); __syncthreads(); }   // buf kt ready; iter kt-1 retired
        if (kt + 2 < S_ / 64) issue_kv(kt + 2, (kt + 2) % 3);
        CP_COMMIT();
        const uint32_t* bufK = Kw + (kt % 3) * 64 * QW;
        const uint32_t* bufV = Vw + (kt % 3) * 64 * QW;

        // ---- S = Q @ K^T (32 rows x 64 keys per warp) ----
        float s[2][8][4];
        #pragma unroll
        for (int mb = 0; mb < 2; ++mb)
            #pragma unroll
            for (int nb = 0; nb < 8; ++nb)
                #pragma unroll
                for (int j = 0; j < 4; ++j) s[mb][nb][j] = 0.0f;

        #pragma unroll
        for (int kk = 0; kk < 4; ++kk) {
            #pragma unroll
            for (int nb = 0; nb < 8; ++nb) {
                uint2 bb = *(const uint2*)(bufK + (8*nb + g) * QW + kk*8 + 2*c);
                mma_f16(s[0][nb], qf[kk][0][0].x, qf[kk][0][1].x,
                                  qf[kk][0][0].y, qf[kk][0][1].y, bb.x, bb.y);
                mma_f16(s[1][nb], qf[kk][1][0].x, qf[kk][1][1].x,
                                  qf[kk][1][0].y, qf[kk][1][1].y, bb.x, bb.y);
            }
        }

        // ---- fused exp + PV ----
        #pragma unroll
        for (int st = 0; st < 4; ++st) {
            uint32_t a[2][4];
            #pragma unroll
            for (int mb = 0; mb < 2; ++mb) {
                float e00 = ex2f(s[mb][2*st][0]   * LOG2E);
                float e01 = ex2f(s[mb][2*st][1]   * LOG2E);
                float e02 = ex2f(s[mb][2*st][2]   * LOG2E);
                float e03 = ex2f(s[mb][2*st][3]   * LOG2E);
                float e10 = ex2f(s[mb][2*st+1][0] * LOG2E);
                float e11 = ex2f(s[mb][2*st+1][1] * LOG2E);
                float e12 = ex2f(s[mb][2*st+1][2] * LOG2E);
                float e13 = ex2f(s[mb][2*st+1][3] * LOG2E);
                lsum[mb][0] += e00 + e01 + e10 + e11;
                lsum[mb][1] += e02 + e03 + e12 + e13;
                a[mb][0] = pack_h2(e00, e01);
                a[mb][1] = pack_h2(e02, e03);
                a[mb][2] = pack_h2(e10, e11);
                a[mb][3] = pack_h2(e12, e13);
            }
            #pragma unroll
            for (int nbd = 0; nbd < 8; ++nbd) {
                uint2 vv = *(const uint2*)(bufV + (8*nbd + g) * QW + st*8 + 2*c);
                mma_f16(o[0][nbd], a[0][0], a[0][1], a[0][2], a[0][3], vv.x, vv.y);
                mma_f16(o[1][nbd], a[1][0], a[1][1], a[1][2], a[1][3], vv.x, vv.y);
            }
        }
    }

    // ---- epilogue: reduce l over quad, normalize, write half context ----
    float inv[2][2];
    #pragma unroll
    for (int mb = 0; mb < 2; ++mb)
        #pragma unroll
        for (int hh = 0; hh < 2; ++hh) {
            float v = lsum[mb][hh];
            v += __shfl_xor_sync(0xffffffffu, v, 1);
            v += __shfl_xor_sync(0xffffffffu, v, 2);
            inv[mb][hh] = 1.0f / v;
        }

    __half* Og = g_Ctxh + (size_t)(b * S_ + q0) * D_ + h * DH_;
    #pragma unroll
    for (int mb = 0; mb < 2; ++mb) {
        int r0 = 32*w + 16*mb + g;
        #pragma unroll
        for (int nbd = 0; nbd < 8; ++nbd) {
            int col = 8*nbd + 2*c;
            *(uint32_t*)(Og + (size_t)r0 * D_ + col) =
                pack_h2(o[mb][nbd][0] * inv[mb][0], o[mb][nbd][1] * inv[mb][0]);
            *(uint32_t*)(Og + (size_t)(r0 + 8) * D_ + col) =
                pack_h2(o[mb][nbd][2] * inv[mb][1], o[mb][nbd][3] * inv[mb][1]);
        }
    }
}

// ---------------------------------------------------------------------------
extern "C" void kernel_launch(void* const* d_in, const int* in_sizes, int n_in,
                              void* d_out, int out_size)
{
    const float* X  = (const float*)d_in[0];
    const float* Wq = (const float*)d_in[1];
    const float* bq = (const float*)d_in[2];
    const float* Wk = (const float*)d_in[3];
    const float* bk = (const float*)d_in[4];
    const float* Wv = (const float*)d_in[5];
    const float* bv = (const float*)d_in[6];
    const float* Wo = (const float*)d_in[7];
    const float* bo = (const float*)d_in[8];
    float* out = (float*)d_out;

    prep<<<XBLOCKS + 1024, 256>>>(X, Wq, Wk, Wv, Wo);

    size_t gsm = (size_t)6 * GSTAGE * sizeof(uint32_t);  // 73,728 B
    cudaFuncSetAttribute(gemm_h, cudaFuncAttributeMaxDynamicSharedMemorySize, (int)gsm);
    gemm_h<<<dim3(M_/128, D_/128, 3), 256, gsm>>>(bq, bk, bv, nullptr, -1);

    size_t shm = (size_t)(128*QW + 3*64*QW + 3*64*QW) * sizeof(uint32_t);  // 81,920 B
    cudaFuncSetAttribute(attn_h, cudaFuncAttributeMaxDynamicSharedMemorySize, (int)shm);
    attn_h<<<dim3(S_ / 128, H_, B_), ATH, shm>>>();

    gemm_h<<<dim3(M_/128, D_/128), 256, gsm>>>(bo, nullptr, nullptr, out, 3);
}

// round 15
// speedup vs baseline: 1.4325x; 1.0320x over previous
#include <cuda_runtime.h>
#include <cuda_fp16.h>
#include <cstdint>

#define B_  2
#define S_  4096
#define H_  8
#define DH_ 64
#define D_  512
#define M_  (B_*S_)   // 8192

// Scratch (allocation-free rule: __device__ globals)
__device__ __half g_Xh[M_*D_];    // X converted to half [token][dim]
__device__ __half g_Wt[4*D_*D_];  // Wq,Wk,Wv,Wo transposed to [n][k], half
__device__ __half g_Q[M_*D_];     // [token][dim], pre-scaled by log2e/8
__device__ __half g_K[M_*D_];     // [token][dim]
__device__ __half g_V[M_*D_];     // TRANSPOSED [dim][token], tokens pair-permuted per 16-group
__device__ __half g_Ctxh[M_*D_];  // attention output, half [token][dim]

// pack two fp32 -> f16x2 word (lo = first arg, hi = second arg)
__device__ __forceinline__ uint32_t pack_h2(float lo, float hi) {
    uint32_t r;
    asm("cvt.rn.f16x2.f32 %0, %1, %2;" : "=r"(r) : "f"(hi), "f"(lo));
    return r;
}

// 2^x on two fp16 values in one MUFU op
__device__ __forceinline__ uint32_t ex2_h2(uint32_t x) {
    uint32_t r;
    asm("ex2.approx.f16x2 %0, %1;" : "=r"(r) : "r"(x));
    return r;
}

// fp16 mma m16n8k16: a = 4x f16x2, b = 2x f16x2, fp32 accum
__device__ __forceinline__ void mma_f16(float c[4],
                                        uint32_t a0, uint32_t a1, uint32_t a2, uint32_t a3,
                                        uint32_t b0, uint32_t b1) {
    asm volatile(
        "mma.sync.aligned.m16n8k16.row.col.f32.f16.f16.f32 "
        "{%0,%1,%2,%3}, {%4,%5,%6,%7}, {%8,%9}, {%0,%1,%2,%3};\n"
        : "+f"(c[0]), "+f"(c[1]), "+f"(c[2]), "+f"(c[3])
        : "r"(a0), "r"(a1), "r"(a2), "r"(a3), "r"(b0), "r"(b1));
}

__device__ __forceinline__ void cp16(void* dst_smem, const void* src_gmem) {
    uint32_t d = (uint32_t)__cvta_generic_to_shared(dst_smem);
    asm volatile("cp.async.cg.shared.global [%0], [%1], 16;" :: "r"(d), "l"(src_gmem));
}
#define CP_COMMIT() asm volatile("cp.async.commit_group;")
#define CP_WAIT1()  asm volatile("cp.async.wait_group 1;")

// token permutation within 16-group: pair p -> slot (p<4 ? 2p : 2(p-4)+1)
__device__ __forceinline__ int vperm(int tok) {
    int p  = (tok >> 1) & 7;
    int pp = (p < 4) ? (2*p) : (2*(p-4)+1);
    return (tok & ~15) | (pp << 1) | (tok & 1);
}

// ---------------------------------------------------------------------------
// Prep (fused): blocks [0, 8192) convert X fp32->half; blocks [8192, 9216)
// transpose+convert the 4 weight matrices to Wt [n][k] half.
// ---------------------------------------------------------------------------
#define XBLOCKS (M_*D_/2/256)   // 8192

__global__ __launch_bounds__(256) void prep(const float* __restrict__ X,
                                            const float* __restrict__ W0,
                                            const float* __restrict__ W1,
                                            const float* __restrict__ W2,
                                            const float* __restrict__ W3)
{
    __shared__ float tl[32][33];
    if (blockIdx.x < XBLOCKS) {
        int i = blockIdx.x * 256 + threadIdx.x;
        float2 v = ((const float2*)X)[i];
        ((uint32_t*)g_Xh)[i] = pack_h2(v.x, v.y);
    } else {
        int bid = blockIdx.x - XBLOCKS;        // 0..1023
        int z = bid >> 8;
        int bx = bid & 15, by = (bid >> 4) & 15;
        const float* W = (z == 0) ? W0 : (z == 1) ? W1 : (z == 2) ? W2 : W3;
        __half* Wt = g_Wt + (size_t)z * D_ * D_;
        int n0 = bx * 32, k0 = by * 32;
        int tx = threadIdx.x & 31, ty = threadIdx.x >> 5;   // 32 x 8
        #pragma unroll
        for (int j = 0; j < 32; j += 8)
            tl[ty + j][tx] = W[(size_t)(k0 + ty + j) * D_ + n0 + tx];
        __syncthreads();
        #pragma unroll
        for (int j = 0; j < 32; j += 8)
            Wt[(size_t)(n0 + ty + j) * D_ + k0 + tx] = __float2half_rn(tl[tx][ty + j]);
    }
}

// ---------------------------------------------------------------------------
// fp16 GEMM (known-good): C = A @ Wt^T + bias, m16n8k16, pair k-relabel.
// 128x128 tile/CTA, 256 threads, 8 warps (4x2), warp tile 32x64.
// k-tile 32, TRIPLE-buffered cp.async, ONE sync per k-iter.
// mode 0: g_Q, (acc+b) * (log2e/8) -- logits come out of QK mma in log2
// domain, so attention needs NO per-element multiply before ex2.
// ---------------------------------------------------------------------------
#define HST 24
#define GSTAGE (128*HST)
#define QSCALE 0.1803368801111204f    // 0.125 * log2(e)

__global__ __launch_bounds__(256, 1) void gemm_h(const float* __restrict__ b0,
                                                 const float* __restrict__ b1,
                                                 const float* __restrict__ b2,
                                                 float* __restrict__ Cout,
                                                 int modesel)
{
    extern __shared__ uint32_t smg[];
    uint32_t* Ah = smg;                 // [3][128*HST]
    uint32_t* Bh = smg + 3*GSTAGE;      // [3][128*HST]

    int mode = (modesel >= 0) ? modesel : (int)blockIdx.z;
    const float* bias = (mode == 0 || mode == 3) ? b0 : (mode == 1 ? b1 : b2);
    const __half* A  = (mode == 3) ? g_Ctxh : g_Xh;
    const __half* Bw = g_Wt + (size_t)mode * D_ * D_;

    int t = threadIdx.x, w = t >> 5, lane = t & 31;
    int g = lane >> 2, c = lane & 3;
    int wm = w & 3, wn = w >> 2;
    int m0 = blockIdx.x * 128, n0 = blockIdx.y * 128;

    auto issue = [&](int kt, int buf) {
        int k0 = kt * 32;
        #pragma unroll
        for (int it = 0; it < 2; ++it) {
            int idx = t + it * 256;
            int r = idx >> 2, cc = idx & 3;
            cp16(Ah + buf*GSTAGE + r*HST + cc*4, A  + (size_t)(m0 + r) * D_ + k0 + cc*8);
            cp16(Bh + buf*GSTAGE + r*HST + cc*4, Bw + (size_t)(n0 + r) * D_ + k0 + cc*8);
        }
    };
    issue(0, 0); CP_COMMIT();
    issue(1, 1); CP_COMMIT();

    float acc[2][8][4];
    #pragma unroll
    for (int mb = 0; mb < 2; ++mb)
        #pragma unroll
        for (int nb = 0; nb < 8; ++nb)
            #pragma unroll
            for (int j = 0; j < 4; ++j) acc[mb][nb][j] = 0.0f;

    for (int kt = 0; kt < 16; ++kt) {
        CP_WAIT1(); __syncthreads();                  // buf kt ready; iter kt-1 retired
        if (kt + 2 < 16) issue(kt + 2, (kt + 2) % 3); // target buf read in iter kt-1
        CP_COMMIT();
        const uint32_t* Ab = Ah + (kt % 3) * GSTAGE;
        const uint32_t* Bb = Bh + (kt % 3) * GSTAGE;
        #pragma unroll
        for (int s = 0; s < 2; ++s) {
            uint2 a0 = *(const uint2*)(Ab + (32*wm + g)      * HST + s*8 + 2*c);
            uint2 a1 = *(const uint2*)(Ab + (32*wm + 8 + g)  * HST + s*8 + 2*c);
            uint2 a2 = *(const uint2*)(Ab + (32*wm + 16 + g) * HST + s*8 + 2*c);
            uint2 a3 = *(const uint2*)(Ab + (32*wm + 24 + g) * HST + s*8 + 2*c);
            #pragma unroll
            for (int nb = 0; nb < 8; ++nb) {
                uint2 bb = *(const uint2*)(Bb + (64*wn + 8*nb + g) * HST + s*8 + 2*c);
                mma_f16(acc[0][nb], a0.x, a1.x, a0.y, a1.y, bb.x, bb.y);
                mma_f16(acc[1][nb], a2.x, a3.x, a2.y, a3.y, bb.x, bb.y);
            }
        }
    }

    // Epilogue
    #pragma unroll
    for (int mb = 0; mb < 2; ++mb) {
        int row = m0 + 32*wm + 16*mb + g;
        #pragma unroll
        for (int nb = 0; nb < 8; ++nb) {
            int col = n0 + 64*wn + 8*nb + 2*c;
            float bv0 = bias[col], bv1 = bias[col + 1];
            float v0 = acc[mb][nb][0] + bv0;
            float v1 = acc[mb][nb][1] + bv1;
            float v2 = acc[mb][nb][2] + bv0;
            float v3 = acc[mb][nb][3] + bv1;
            if (mode == 0) {
                *(uint32_t*)(g_Q + (size_t)row * D_ + col) =
                    pack_h2(v0 * QSCALE, v1 * QSCALE);
                *(uint32_t*)(g_Q + (size_t)(row + 8) * D_ + col) =
                    pack_h2(v2 * QSCALE, v3 * QSCALE);
            } else if (mode == 1) {
                *(uint32_t*)(g_K + (size_t)row * D_ + col)       = pack_h2(v0, v1);
                *(uint32_t*)(g_K + (size_t)(row + 8) * D_ + col) = pack_h2(v2, v3);
            } else if (mode == 2) {
                g_V[(size_t)col       * M_ + vperm(row)]     = __float2half_rn(v0);
                g_V[(size_t)(col + 1) * M_ + vperm(row)]     = __float2half_rn(v1);
                g_V[(size_t)col       * M_ + vperm(row + 8)] = __float2half_rn(v2);
                g_V[(size_t)(col + 1) * M_ + vperm(row + 8)] = __float2half_rn(v3);
            } else {
                *(float2*)(Cout + (size_t)row * D_ + col)       = make_float2(v0, v1);
                *(float2*)(Cout + (size_t)(row + 8) * D_ + col) = make_float2(v2, v3);
            }
        }
    }
}

// ---------------------------------------------------------------------------
// Flash attention, fp16 mma m16n8k16, f16x2 exp (half the MUFU ops, outputs
// ARE the PV A-fragment words), lsum via HADD2 with per-tile fp32 flush.
// Q pre-scaled by log2e/8 so QK mma emits log2-domain logits directly.
// 128 threads (4 warps), 128 queries/CTA, 2 CTAs/SM, warp = 32 rows.
// 64-key tiles, triple-buffered cp.async, one sync per tile.
// ---------------------------------------------------------------------------
#define QW 40
#define ATH 128

__global__ __launch_bounds__(ATH, 2) void attn_h()
{
    extern __shared__ char smc[];
    uint32_t* Qw = (uint32_t*)smc;                 // [128][QW]
    uint32_t* Kw = Qw + 128*QW;                    // [3][64][QW]
    uint32_t* Vw = Kw + 3*64*QW;                   // [3][64][QW]

    int t = threadIdx.x, w = t >> 5, lane = t & 31;
    int g = lane >> 2, c = lane & 3;
    int b = blockIdx.z, h = blockIdx.y;
    int q0 = blockIdx.x * 128;

    const __half* Qg  = g_Q + (size_t)(b * S_ + q0) * D_ + h * DH_;
    const __half* Kg  = g_K + (size_t)b * S_ * D_ + h * DH_;
    const __half* Vtg = g_V + (size_t)(h * DH_) * M_ + b * S_;   // [dim][token]

    auto issue_kv = [&](int kt, int buf) {
        uint32_t* kd = Kw + buf * 64 * QW;
        uint32_t* vd = Vw + buf * 64 * QW;
        #pragma unroll
        for (int it = 0; it < 4; ++it) {
            int idx = t + it * ATH;
            int row = idx >> 3, c4 = idx & 7;
            cp16(kd + row*QW + c4*4, Kg + (size_t)(kt*64 + row) * D_ + c4*8);
            cp16(vd + row*QW + c4*4, Vtg + (size_t)row * M_ + kt*64 + c4*8);
        }
    };

    // Prologue: G0 = Q + KV0; G1 = KV1
    #pragma unroll
    for (int it = 0; it < 8; ++it) {
        int idx = t + it * ATH;
        int row = idx >> 3, c4 = idx & 7;
        cp16(Qw + row*QW + c4*4, Qg + (size_t)row * D_ + c4*8);
    }
    issue_kv(0, 0); CP_COMMIT();
    issue_kv(1, 1); CP_COMMIT();

    CP_WAIT1(); __syncthreads();     // G0 (Q + KV0) complete

    // Hoist Q fragments: qf[kk][mb][i], i=0 -> row 32w+16mb+g, i=1 -> +8
    uint2 qf[4][2][2];
    #pragma unroll
    for (int kk = 0; kk < 4; ++kk)
        #pragma unroll
        for (int mb = 0; mb < 2; ++mb) {
            qf[kk][mb][0] = *(const uint2*)(Qw + (32*w + 16*mb + g)     * QW + kk*8 + 2*c);
            qf[kk][mb][1] = *(const uint2*)(Qw + (32*w + 16*mb + 8 + g) * QW + kk*8 + 2*c);
        }

    float o[2][8][4];
    #pragma unroll
    for (int mb = 0; mb < 2; ++mb)
        #pragma unroll
        for (int nb = 0; nb < 8; ++nb)
            #pragma unroll
            for (int j = 0; j < 4; ++j) o[mb][nb][j] = 0.0f;
    float lsum[2][2] = {{0.0f, 0.0f}, {0.0f, 0.0f}};

    for (int kt = 0; kt < S_ / 64; ++kt) {
        if (kt > 0) { CP_WAIT1(); __syncthreads(); }   // buf kt ready; iter kt-1 retired
        if (kt + 2 < S_ / 64) issue_kv(kt + 2, (kt + 2) % 3);
        CP_COMMIT();
        const uint32_t* bufK = Kw + (kt % 3) * 64 * QW;
        const uint32_t* bufV = Vw + (kt % 3) * 64 * QW;

        // ---- S = Q @ K^T (32 rows x 64 keys per warp), log2-domain ----
        float s[2][8][4];
        #pragma unroll
        for (int mb = 0; mb < 2; ++mb)
            #pragma unroll
            for (int nb = 0; nb < 8; ++nb)
                #pragma unroll
                for (int j = 0; j < 4; ++j) s[mb][nb][j] = 0.0f;

        #pragma unroll
        for (int kk = 0; kk < 4; ++kk) {
            #pragma unroll
            for (int nb = 0; nb < 8; ++nb) {
                uint2 bb = *(const uint2*)(bufK + (8*nb + g) * QW + kk*8 + 2*c);
                mma_f16(s[0][nb], qf[kk][0][0].x, qf[kk][0][1].x,
                                  qf[kk][0][0].y, qf[kk][0][1].y, bb.x, bb.y);
                mma_f16(s[1][nb], qf[kk][1][0].x, qf[kk][1][1].x,
                                  qf[kk][1][0].y, qf[kk][1][1].y, bb.x, bb.y);
            }
        }

        // ---- fused f16x2 exp + PV; per-tile half2 lsum, fp32 flush ----
        __half2 lh[2][2];
        #pragma unroll
        for (int mb = 0; mb < 2; ++mb) {
            lh[mb][0] = __float2half2_rn(0.0f);
            lh[mb][1] = __float2half2_rn(0.0f);
        }

        #pragma unroll
        for (int st = 0; st < 4; ++st) {
            uint32_t a[2][4];
            #pragma unroll
            for (int mb = 0; mb < 2; ++mb) {
                a[mb][0] = ex2_h2(pack_h2(s[mb][2*st][0],   s[mb][2*st][1]));
                a[mb][1] = ex2_h2(pack_h2(s[mb][2*st][2],   s[mb][2*st][3]));
                a[mb][2] = ex2_h2(pack_h2(s[mb][2*st+1][0], s[mb][2*st+1][1]));
                a[mb][3] = ex2_h2(pack_h2(s[mb][2*st+1][2], s[mb][2*st+1][3]));
                // rows g -> a0, a2 ; rows g+8 -> a1, a3
                lh[mb][0] = __hadd2(lh[mb][0],
                    __hadd2(*(__half2*)&a[mb][0], *(__half2*)&a[mb][2]));
                lh[mb][1] = __hadd2(lh[mb][1],
                    __hadd2(*(__half2*)&a[mb][1], *(__half2*)&a[mb][3]));
            }
            #pragma unroll
            for (int nbd = 0; nbd < 8; ++nbd) {
                uint2 vv = *(const uint2*)(bufV + (8*nbd + g) * QW + st*8 + 2*c);
                mma_f16(o[0][nbd], a[0][0], a[0][1], a[0][2], a[0][3], vv.x, vv.y);
                mma_f16(o[1][nbd], a[1][0], a[1][1], a[1][2], a[1][3], vv.x, vv.y);
            }
        }

        #pragma unroll
        for (int mb = 0; mb < 2; ++mb) {
            float2 f0 = __half22float2(lh[mb][0]);
            float2 f1 = __half22float2(lh[mb][1]);
            lsum[mb][0] += f0.x + f0.y;
            lsum[mb][1] += f1.x + f1.y;
        }
    }

    // ---- epilogue: reduce l over quad, normalize, write half context ----
    float inv[2][2];
    #pragma unroll
    for (int mb = 0; mb < 2; ++mb)
        #pragma unroll
        for (int hh = 0; hh < 2; ++hh) {
            float v = lsum[mb][hh];
            v += __shfl_xor_sync(0xffffffffu, v, 1);
            v += __shfl_xor_sync(0xffffffffu, v, 2);
            inv[mb][hh] = 1.0f / v;
        }

    __half* Og = g_Ctxh + (size_t)(b * S_ + q0) * D_ + h * DH_;
    #pragma unroll
    for (int mb = 0; mb < 2; ++mb) {
        int r0 = 32*w + 16*mb + g;
        #pragma unroll
        for (int nbd = 0; nbd < 8; ++nbd) {
            int col = 8*nbd + 2*c;
            *(uint32_t*)(Og + (size_t)r0 * D_ + col) =
                pack_h2(o[mb][nbd][0] * inv[mb][0], o[mb][nbd][1] * inv[mb][0]);
            *(uint32_t*)(Og + (size_t)(r0 + 8) * D_ + col) =
                pack_h2(o[mb][nbd][2] * inv[mb][1], o[mb][nbd][3] * inv[mb][1]);
        }
    }
}

// ---------------------------------------------------------------------------
extern "C" void kernel_launch(void* const* d_in, const int* in_sizes, int n_in,
                              void* d_out, int out_size)
{
    const float* X  = (const float*)d_in[0];
    const float* Wq = (const float*)d_in[1];
    const float* bq = (const float*)d_in[2];
    const float* Wk = (const float*)d_in[3];
    const float* bk = (const float*)d_in[4];
    const float* Wv = (const float*)d_in[5];
    const float* bv = (const float*)d_in[6];
    const float* Wo = (const float*)d_in[7];
    const float* bo = (const float*)d_in[8];
    float* out = (float*)d_out;

    prep<<<XBLOCKS + 1024, 256>>>(X, Wq, Wk, Wv, Wo);

    size_t gsm = (size_t)6 * GSTAGE * sizeof(uint32_t);  // 73,728 B
    cudaFuncSetAttribute(gemm_h, cudaFuncAttributeMaxDynamicSharedMemorySize, (int)gsm);
    gemm_h<<<dim3(M_/128, D_/128, 3), 256, gsm>>>(bq, bk, bv, nullptr, -1);

    size_t shm = (size_t)(128*QW + 3*64*QW + 3*64*QW) * sizeof(uint32_t);  // 81,920 B
    cudaFuncSetAttribute(attn_h, cudaFuncAttributeMaxDynamicSharedMemorySize, (int)shm);
    attn_h<<<dim3(S_ / 128, H_, B_), ATH, shm>>>();

    gemm_h<<<dim3(M_/128, D_/128), 256, gsm>>>(bo, nullptr, nullptr, out, 3);
}